// round 1
// baseline (speedup 1.0000x reference)
#include <cuda_runtime.h>
#include <cstdint>

#define BATCH 8
#define CH    512
#define NPIX  1024
#define HEADS 8
#define HD    64
#define EPSBN 1e-5f

// -------- static scratch (allocation-free rule: __device__ globals) --------
__device__ float g_xs[BATCH * CH * NPIX];
__device__ float g_q [BATCH * CH * NPIX];
__device__ float g_k [BATCH * CH * NPIX];
__device__ float g_v [BATCH * CH * NPIX];
__device__ float g_os[BATCH * CH * NPIX];
__device__ float g_M [BATCH * HEADS * HD * HD];

// spike: round(clamp(x,0,4))/4, round-half-even to match jnp.round
__device__ __forceinline__ float spikef(float x) {
    x = fminf(fmaxf(x, 0.0f), 4.0f);
    return rintf(x) * 0.25f;
}

// ---------------------------------------------------------------------------
// K1: xs = spike(x), vectorized float4
// ---------------------------------------------------------------------------
__global__ void spike_kernel(const float* __restrict__ x) {
    int i = blockIdx.x * blockDim.x + threadIdx.x;   // 1,048,576 float4s
    float4 a = ((const float4*)x)[i];
    a.x = spikef(a.x); a.y = spikef(a.y); a.z = spikef(a.z); a.w = spikef(a.w);
    ((float4*)g_xs)[i] = a;
}

// ---------------------------------------------------------------------------
// K2/K5: per-batch SGEMM  Y[o,n] = sum_c W[o,c] * X[b,c,n], then BN (+spike)
// 128x128 block tile, BK=8, 8x8 per thread (split 4+4 for conflict-free smem)
// ---------------------------------------------------------------------------
template <bool SPIKE>
__global__ __launch_bounds__(256)
void conv_bn_kernel(const float* __restrict__ Wt,   // [CH, CH] row-major (o,c)
                    const float* __restrict__ X,    // [B, CH, NPIX]
                    const float* __restrict__ gg, const float* __restrict__ bb,
                    const float* __restrict__ mm, const float* __restrict__ vv,
                    float* __restrict__ Y)          // [B, CH, NPIX]
{
    const int b = blockIdx.z;
    const float* Xb = X + (size_t)b * CH * NPIX;
    float*       Yb = Y + (size_t)b * CH * NPIX;
    const int tile_n = blockIdx.x * 128;
    const int tile_m = blockIdx.y * 128;

    __shared__ float As[8][128];
    __shared__ float Bs[8][128];

    const int tid = threadIdx.x;
    const int tx = tid & 15, ty = tid >> 4;

    const int arow = tid >> 1,  acol = (tid & 1) * 4;   // A tile: 128 rows x 8 k
    const int brow = tid >> 5,  bcol = (tid & 31) * 4;  // B tile: 8 k x 128 cols

    float acc[8][8];
#pragma unroll
    for (int i = 0; i < 8; i++)
#pragma unroll
        for (int j = 0; j < 8; j++) acc[i][j] = 0.0f;

    for (int k0 = 0; k0 < CH; k0 += 8) {
        float4 a = *(const float4*)(Wt + (size_t)(tile_m + arow) * CH + k0 + acol);
        As[acol + 0][arow] = a.x;
        As[acol + 1][arow] = a.y;
        As[acol + 2][arow] = a.z;
        As[acol + 3][arow] = a.w;
        *(float4*)&Bs[brow][bcol] =
            *(const float4*)(Xb + (size_t)(k0 + brow) * NPIX + tile_n + bcol);
        __syncthreads();

#pragma unroll
        for (int k = 0; k < 8; k++) {
            float ra[8], rb[8];
            *(float4*)&ra[0] = *(float4*)&As[k][ty * 4];
            *(float4*)&ra[4] = *(float4*)&As[k][64 + ty * 4];
            *(float4*)&rb[0] = *(float4*)&Bs[k][tx * 4];
            *(float4*)&rb[4] = *(float4*)&Bs[k][64 + tx * 4];
#pragma unroll
            for (int i = 0; i < 8; i++)
#pragma unroll
                for (int j = 0; j < 8; j++)
                    acc[i][j] = fmaf(ra[i], rb[j], acc[i][j]);
        }
        __syncthreads();
    }

#pragma unroll
    for (int i = 0; i < 8; i++) {
        int row = tile_m + ((i < 4) ? (ty * 4 + i) : (64 + ty * 4 + i - 4));
        float s    = gg[row] / sqrtf(vv[row] + EPSBN);
        float beta = bb[row] - mm[row] * s;
#pragma unroll
        for (int j = 0; j < 8; j++) {
            int col = tile_n + ((j < 4) ? (tx * 4 + j) : (64 + tx * 4 + j - 4));
            float y = fmaf(acc[i][j], s, beta);
            if (SPIKE) y = spikef(y);
            Yb[(size_t)row * NPIX + col] = y;
        }
    }
}

// ---------------------------------------------------------------------------
// K3a: zero M
// ---------------------------------------------------------------------------
__global__ void zero_M_kernel() {
    ((float4*)g_M)[blockIdx.x * 256 + threadIdx.x] = make_float4(0.f, 0.f, 0.f, 0.f);
}

// ---------------------------------------------------------------------------
// K3b: M[b,h,d,d'] += sum_n k[b,h*64+d,n] * v[b,h*64+d',n]   (N split 4 ways,
// atomicAdd is exact: all summands are multiples of 1/16, sums < 2^14)
// grid = (4, 64)
// ---------------------------------------------------------------------------
__global__ __launch_bounds__(256)
void ktv_kernel() {
    const int bh = blockIdx.y;
    const int b = bh >> 3, h = bh & 7;
    const float* Kb = g_k + (size_t)b * CH * NPIX + (size_t)h * HD * NPIX;
    const float* Vb = g_v + (size_t)b * CH * NPIX + (size_t)h * HD * NPIX;

    __shared__ float ks[64][33];
    __shared__ float vs[64][33];

    const int tid = threadIdx.x;
    const int tx = tid & 15, ty = tid >> 4;
    const int lr = tid >> 2, lc = (tid & 3) * 8;

    float acc[4][4];
#pragma unroll
    for (int i = 0; i < 4; i++)
#pragma unroll
        for (int j = 0; j < 4; j++) acc[i][j] = 0.0f;

    const int n_beg = blockIdx.x * 256;
    for (int n0 = n_beg; n0 < n_beg + 256; n0 += 32) {
        float4 a0 = *(const float4*)(Kb + (size_t)lr * NPIX + n0 + lc);
        float4 a1 = *(const float4*)(Kb + (size_t)lr * NPIX + n0 + lc + 4);
        ks[lr][lc + 0] = a0.x; ks[lr][lc + 1] = a0.y; ks[lr][lc + 2] = a0.z; ks[lr][lc + 3] = a0.w;
        ks[lr][lc + 4] = a1.x; ks[lr][lc + 5] = a1.y; ks[lr][lc + 6] = a1.z; ks[lr][lc + 7] = a1.w;
        float4 b0 = *(const float4*)(Vb + (size_t)lr * NPIX + n0 + lc);
        float4 b1 = *(const float4*)(Vb + (size_t)lr * NPIX + n0 + lc + 4);
        vs[lr][lc + 0] = b0.x; vs[lr][lc + 1] = b0.y; vs[lr][lc + 2] = b0.z; vs[lr][lc + 3] = b0.w;
        vs[lr][lc + 4] = b1.x; vs[lr][lc + 5] = b1.y; vs[lr][lc + 6] = b1.z; vs[lr][lc + 7] = b1.w;
        __syncthreads();

#pragma unroll
        for (int nn = 0; nn < 32; nn++) {
            float ra[4], rb[4];
#pragma unroll
            for (int i = 0; i < 4; i++) ra[i] = ks[ty * 4 + i][nn];
#pragma unroll
            for (int j = 0; j < 4; j++) rb[j] = vs[tx * 4 + j][nn];
#pragma unroll
            for (int i = 0; i < 4; i++)
#pragma unroll
                for (int j = 0; j < 4; j++)
                    acc[i][j] = fmaf(ra[i], rb[j], acc[i][j]);
        }
        __syncthreads();
    }

    float* Mp = g_M + (size_t)bh * HD * HD;
#pragma unroll
    for (int i = 0; i < 4; i++)
#pragma unroll
        for (int j = 0; j < 4; j++)
            atomicAdd(&Mp[(ty * 4 + i) * HD + tx * 4 + j], acc[i][j]);
}

// ---------------------------------------------------------------------------
// K4: os[b, h*64+d', n] = spike( 0.25 * sum_d q[b,h*64+d,n] * M[b,h,d,d'] )
// grid = (8 n-tiles of 128, 64 bh)
// ---------------------------------------------------------------------------
__global__ __launch_bounds__(256)
void qm_kernel() {
    const int bh = blockIdx.y;
    const int b = bh >> 3, h = bh & 7;
    const int tile_n = blockIdx.x * 128;
    const float* Qb = g_q + (size_t)b * CH * NPIX + (size_t)h * HD * NPIX;

    __shared__ float Ms[64 * 64];       // M[d][d']
    __shared__ float qs[64][128];       // q[d][n]

    const int tid = threadIdx.x;

    const float4* Msrc = (const float4*)(g_M + (size_t)bh * HD * HD);
#pragma unroll
    for (int l = 0; l < 4; l++)
        ((float4*)Ms)[tid + l * 256] = Msrc[tid + l * 256];

#pragma unroll
    for (int l = 0; l < 8; l++) {
        int fi = tid + l * 256;
        int row = fi >> 5, c4 = (fi & 31) * 4;
        *(float4*)&qs[row][c4] =
            *(const float4*)(Qb + (size_t)row * NPIX + tile_n + c4);
    }
    __syncthreads();

    const int tx = tid & 31, ty = tid >> 5;   // cols n = tx*4.., rows d' = ty*8..
    float acc[8][4];
#pragma unroll
    for (int i = 0; i < 8; i++)
#pragma unroll
        for (int j = 0; j < 4; j++) acc[i][j] = 0.0f;

#pragma unroll 8
    for (int k = 0; k < 64; k++) {
        float rb[4];
        *(float4*)rb = *(float4*)&qs[k][tx * 4];
#pragma unroll
        for (int i = 0; i < 8; i++) {
            float ra = Ms[k * 64 + ty * 8 + i];
#pragma unroll
            for (int j = 0; j < 4; j++)
                acc[i][j] = fmaf(ra, rb[j], acc[i][j]);
        }
    }

    float* Ob = g_os + (size_t)b * CH * NPIX + (size_t)h * HD * NPIX;
#pragma unroll
    for (int i = 0; i < 8; i++) {
        int dp = ty * 8 + i;
#pragma unroll
        for (int j = 0; j < 4; j++) {
            float y = acc[i][j] * 0.25f;   // (hd^-0.5) * 2 = 0.25
            Ob[(size_t)dp * NPIX + tile_n + tx * 4 + j] = spikef(y);
        }
    }
}

// ---------------------------------------------------------------------------
// launch
// ---------------------------------------------------------------------------
extern "C" void kernel_launch(void* const* d_in, const int* in_sizes, int n_in,
                              void* d_out, int out_size) {
    (void)in_sizes; (void)n_in; (void)out_size;
    const float* x  = (const float*)d_in[0];
    const float* qw = (const float*)d_in[1];
    const float* qg = (const float*)d_in[2];
    const float* qb = (const float*)d_in[3];
    const float* qm = (const float*)d_in[4];
    const float* qv = (const float*)d_in[5];
    const float* kw = (const float*)d_in[6];
    const float* kg = (const float*)d_in[7];
    const float* kb = (const float*)d_in[8];
    const float* km = (const float*)d_in[9];
    const float* kv = (const float*)d_in[10];
    const float* vw = (const float*)d_in[11];
    const float* vg = (const float*)d_in[12];
    const float* vb = (const float*)d_in[13];
    const float* vm = (const float*)d_in[14];
    const float* vv = (const float*)d_in[15];
    const float* pw = (const float*)d_in[16];
    const float* pg = (const float*)d_in[17];
    const float* pb = (const float*)d_in[18];
    const float* pm = (const float*)d_in[19];
    const float* pv = (const float*)d_in[20];
    float* out = (float*)d_out;

    float *xs, *q, *k, *v, *os;
    cudaGetSymbolAddress((void**)&xs, g_xs);
    cudaGetSymbolAddress((void**)&q,  g_q);
    cudaGetSymbolAddress((void**)&k,  g_k);
    cudaGetSymbolAddress((void**)&v,  g_v);
    cudaGetSymbolAddress((void**)&os, g_os);

    spike_kernel<<<4096, 256>>>(x);

    dim3 cgrid(NPIX / 128, CH / 128, BATCH);   // (8, 4, 8)
    conv_bn_kernel<true ><<<cgrid, 256>>>(qw, xs, qg, qb, qm, qv, q);
    conv_bn_kernel<true ><<<cgrid, 256>>>(kw, xs, kg, kb, km, kv, k);
    conv_bn_kernel<true ><<<cgrid, 256>>>(vw, xs, vg, vb, vm, vv, v);

    zero_M_kernel<<<256, 256>>>();
    ktv_kernel<<<dim3(4, 64), 256>>>();
    qm_kernel <<<dim3(8, 64), 256>>>();

    conv_bn_kernel<false><<<cgrid, 256>>>(pw, os, pg, pb, pm, pv, out);
}

// round 4
// speedup vs baseline: 2.2334x; 2.2334x over previous
#include <cuda_runtime.h>
#include <cuda_fp16.h>
#include <cstdint>

#define BATCH 8
#define CH    512
#define NPIX  1024
#define HEADS 8
#define HD    64
#define EPSBN 1e-5f

// ---------------- static scratch (no allocs allowed) ----------------
__device__ __half g_xs_t [BATCH * NPIX * CH];   // spiked x, transposed [b][n][c]
__device__ __half g_q    [BATCH * CH * NPIX];   // [b][c][n]
__device__ __half g_k    [BATCH * CH * NPIX];
__device__ __half g_v    [BATCH * CH * NPIX];
__device__ __half g_os_t [BATCH * NPIX * CH];   // spiked attn out, [b][n][c]
__device__ float  g_M    [BATCH * HEADS * HD * HD];
__device__ __half g_wsplit[4 * CH * (2 * CH)];  // per weight: [o][c<512]=hi, [o][512+c]=lo

__device__ __forceinline__ float spikef(float x) {
    x = fminf(fmaxf(x, 0.0f), 4.0f);
    return rintf(x) * 0.25f;           // round-half-even == jnp.round
}

// ---------------- PTX helpers (all baseline sm_80+ features) ----------------
__device__ __forceinline__ uint32_t smem_u32(const void* p) {
    uint32_t a;
    asm("{ .reg .u64 t; cvta.to.shared.u64 t, %1; cvt.u32.u64 %0, t; }" : "=r"(a) : "l"(p));
    return a;
}
#define CP_ASYNC16(dst, src) \
    asm volatile("cp.async.cg.shared.global [%0], [%1], 16;" :: "r"(dst), "l"(src))
#define CP_COMMIT()  asm volatile("cp.async.commit_group;" ::: "memory")
#define CP_WAIT1()   asm volatile("cp.async.wait_group 1;" ::: "memory")
#define CP_WAIT0()   asm volatile("cp.async.wait_group 0;" ::: "memory")

__device__ __forceinline__ void ldsm_x4(uint32_t& r0, uint32_t& r1, uint32_t& r2, uint32_t& r3,
                                        uint32_t addr) {
    asm volatile("ldmatrix.sync.aligned.m8n8.x4.shared.b16 {%0,%1,%2,%3}, [%4];"
                 : "=r"(r0), "=r"(r1), "=r"(r2), "=r"(r3) : "r"(addr));
}
__device__ __forceinline__ void mma16816(float* d, const uint32_t* a, const uint32_t* b) {
    asm volatile(
        "mma.sync.aligned.m16n8k16.row.col.f32.f16.f16.f32 "
        "{%0,%1,%2,%3},{%4,%5,%6,%7},{%8,%9},{%0,%1,%2,%3};"
        : "+f"(d[0]), "+f"(d[1]), "+f"(d[2]), "+f"(d[3])
        : "r"(a[0]), "r"(a[1]), "r"(a[2]), "r"(a[3]), "r"(b[0]), "r"(b[1]));
}
#define SW128(off) ((off) ^ (((off) >> 3) & 0x70))

// ---------------------------------------------------------------------------
// K0: split each fp32 weight into two fp16 halves, K-concatenated
// ---------------------------------------------------------------------------
__global__ void wsplit_kernel(const float* __restrict__ w0, const float* __restrict__ w1,
                              const float* __restrict__ w2, const float* __restrict__ w3) {
    const float* W[4] = {w0, w1, w2, w3};
    int wi = blockIdx.y;
    int idx = blockIdx.x * 256 + threadIdx.x;      // 0 .. 262143
    int o = idx >> 9, c = idx & 511;
    float w = W[wi][o * 512 + c];
    __half h1 = __float2half_rn(w);
    __half h2 = __float2half_rn(w - __half2float(h1));
    __half* dst = g_wsplit + (size_t)(wi * 512 + o) * 1024;
    dst[c]       = h1;
    dst[512 + c] = h2;
}

// ---------------------------------------------------------------------------
// K1: xs_t[b][n][c] = fp16(spike(x[b][c][n]))  -- transpose via smem tile
// ---------------------------------------------------------------------------
__global__ void spike_t_kernel(const float* __restrict__ x) {
    __shared__ float tile[32][33];
    int b = blockIdx.z, n0 = blockIdx.x * 32, c0 = blockIdx.y * 32;
    int tx = threadIdx.x, ty = threadIdx.y;
    const float* xb = x + (size_t)b * CH * NPIX;
#pragma unroll
    for (int i = 0; i < 4; i++)
        tile[ty + i * 8][tx] = spikef(xb[(size_t)(c0 + ty + i * 8) * NPIX + n0 + tx]);
    __syncthreads();
    __half* ob = g_xs_t + (size_t)b * NPIX * CH;
#pragma unroll
    for (int i = 0; i < 4; i++)
        ob[(size_t)(n0 + ty + i * 8) * CH + c0 + tx] = __float2half_rn(tile[tx][ty + i * 8]);
}

// ---------------------------------------------------------------------------
// K2: mma.sync conv_bn GEMM.  D[o,n] = sum_{k<1024} Wsp[o,k] * Bact[n, k%512]
// 128x128 tile, BK=64, cp.async double buffer, SW128 smem, 8 warps (2m x 4n),
// warp tile 64x32, mma m16n8k16 fp16->fp32. Epilogue: BN (+spike).
// grid (8 ntiles, 4 otiles, 8 batch), 256 threads, 66KB dyn smem
// ---------------------------------------------------------------------------
template <bool SPIKE, typename OutT>
__global__ __launch_bounds__(256)
void conv_mma_kernel(const __half* __restrict__ Wsp,   // [512][1024]
                     const __half* __restrict__ Bact,  // [B][1024][512]
                     const float* __restrict__ gg, const float* __restrict__ bb,
                     const float* __restrict__ mm, const float* __restrict__ vv,
                     OutT* __restrict__ Y)             // [B][512][1024]
{
    extern __shared__ char dsm[];
    const int tid  = threadIdx.x;
    const int wid  = tid >> 5, lane = tid & 31;
    const int b      = blockIdx.z;
    const int tile_n = blockIdx.x * 128;
    const int tile_m = blockIdx.y * 128;
    const int warp_m = (wid & 1) * 64;
    const int warp_n = (wid >> 1) * 32;

    uint32_t base = (smem_u32(dsm) + 1023) & ~1023u;
    uint32_t bufA[2] = {base,         base + 32768};
    uint32_t bufB[2] = {base + 16384, base + 49152};

    const __half* Bb = Bact + (size_t)b * NPIX * CH;
    const __half* Arow = Wsp + (size_t)(tile_m + (tid >> 1)) * 1024 + (tid & 1) * 32;
    const __half* Brow = Bb  + (size_t)(tile_n + (tid >> 1)) * 512  + (tid & 1) * 32;

    // staging dsts: row = tid>>1, chunks (tid&1)*4 + i  (16B each), SW128
    uint32_t stg[4];
#pragma unroll
    for (int i = 0; i < 4; i++) {
        uint32_t off = (uint32_t)(tid >> 1) * 128 + ((tid & 1) * 4 + i) * 16;
        stg[i] = SW128(off);
    }

    // ldmatrix source offsets (tile-relative, swizzled at use)
    const uint32_t aoff = (uint32_t)(warp_m + (lane & 15)) * 128 + (lane >> 4) * 16;
    const uint32_t boff = (uint32_t)(warp_n + ((lane >> 4) & 1) * 8 + (lane & 7)) * 128
                        + ((lane >> 3) & 1) * 16;

    float acc[4][4][4];
#pragma unroll
    for (int mt = 0; mt < 4; mt++)
#pragma unroll
        for (int nt = 0; nt < 4; nt++)
#pragma unroll
            for (int e = 0; e < 4; e++) acc[mt][nt][e] = 0.0f;

    // prologue: load stage 0 (ch=0)
#pragma unroll
    for (int i = 0; i < 4; i++) {
        CP_ASYNC16(bufA[0] + stg[i], Arow + i * 8);
        CP_ASYNC16(bufB[0] + stg[i], Brow + i * 8);
    }
    CP_COMMIT();

#pragma unroll 1
    for (int ch = 0; ch < 16; ch++) {
        if (ch < 15) {
            int nb = (ch + 1) & 1;
            const __half* An = Arow + (size_t)(ch + 1) * 64;
            const __half* Bn = Brow + (size_t)((ch + 1) & 7) * 64;
#pragma unroll
            for (int i = 0; i < 4; i++) {
                CP_ASYNC16(bufA[nb] + stg[i], An + i * 8);
                CP_ASYNC16(bufB[nb] + stg[i], Bn + i * 8);
            }
            CP_COMMIT();
            CP_WAIT1();
        } else {
            CP_WAIT0();
        }
        __syncthreads();

        const uint32_t A0 = bufA[ch & 1], B0 = bufB[ch & 1];
#pragma unroll
        for (int s = 0; s < 4; s++) {
            uint32_t af[4][4], bf[2][4];
#pragma unroll
            for (int mt = 0; mt < 4; mt++)
                ldsm_x4(af[mt][0], af[mt][1], af[mt][2], af[mt][3],
                        A0 + SW128(aoff + mt * 2048 + s * 32));
#pragma unroll
            for (int p = 0; p < 2; p++)
                ldsm_x4(bf[p][0], bf[p][1], bf[p][2], bf[p][3],
                        B0 + SW128(boff + p * 2048 + s * 32));
#pragma unroll
            for (int mt = 0; mt < 4; mt++)
#pragma unroll
                for (int nt = 0; nt < 4; nt++)
                    mma16816(acc[mt][nt], af[mt], &bf[nt >> 1][(nt & 1) * 2]);
        }
        __syncthreads();
    }

    // -------- epilogue: BN (+spike), direct register->gmem --------
    const int r0 = lane >> 2;                  // row-in-m16 (0..7); +8 for c2/c3
    const int c0 = (lane & 3) * 2;             // col-in-n8 (even)
#pragma unroll
    for (int mt = 0; mt < 4; mt++) {
#pragma unroll
        for (int half = 0; half < 2; half++) {
            const int o = tile_m + warp_m + mt * 16 + r0 + half * 8;
            const float s    = gg[o] / sqrtf(vv[o] + EPSBN);
            const float beta = bb[o] - mm[o] * s;
            OutT* yrow = Y + ((size_t)b * 512 + o) * 1024;
#pragma unroll
            for (int nt = 0; nt < 4; nt++) {
                const int n = tile_n + warp_n + nt * 8 + c0;
                float y0 = fmaf(acc[mt][nt][half * 2 + 0], s, beta);
                float y1 = fmaf(acc[mt][nt][half * 2 + 1], s, beta);
                if (SPIKE) {
                    __half2 hh = __floats2half2_rn(spikef(y0), spikef(y1));
                    *reinterpret_cast<__half2*>((__half*)yrow + n) = hh;
                } else {
                    *reinterpret_cast<float2*>((float*)yrow + n) = make_float2(y0, y1);
                }
            }
        }
    }
}

// ---------------------------------------------------------------------------
// K3a: zero M
// ---------------------------------------------------------------------------
__global__ void zero_M_kernel() {
    ((float4*)g_M)[blockIdx.x * 256 + threadIdx.x] = make_float4(0.f, 0.f, 0.f, 0.f);
}

// ---------------------------------------------------------------------------
// K3b: M[b,h,d,d'] += sum_n k[b,hd+d,n] * v[b,hd+d',n]  (fp16 in, exact fp32 acc)
// grid (4 n-splits, 64 bh), 256 thr
// ---------------------------------------------------------------------------
__global__ __launch_bounds__(256)
void ktv_kernel() {
    const int bh = blockIdx.y;
    const int b = bh >> 3, h = bh & 7;
    const __half* Kb = g_k + (size_t)b * CH * NPIX + (size_t)h * HD * NPIX;
    const __half* Vb = g_v + (size_t)b * CH * NPIX + (size_t)h * HD * NPIX;

    __shared__ float ks[64][33];
    __shared__ float vs[64][33];

    const int tid = threadIdx.x;
    const int tx = tid & 15, ty = tid >> 4;
    const int lr = tid >> 2, lc = (tid & 3) * 8;

    float acc[4][4];
#pragma unroll
    for (int i = 0; i < 4; i++)
#pragma unroll
        for (int j = 0; j < 4; j++) acc[i][j] = 0.0f;

    const int n_beg = blockIdx.x * 256;
    for (int n0 = n_beg; n0 < n_beg + 256; n0 += 32) {
        int4 rk = *(const int4*)(Kb + (size_t)lr * NPIX + n0 + lc);
        int4 rv = *(const int4*)(Vb + (size_t)lr * NPIX + n0 + lc);
        const __half2* hk = (const __half2*)&rk;
        const __half2* hv = (const __half2*)&rv;
#pragma unroll
        for (int p = 0; p < 4; p++) {
            float2 fk = __half22float2(hk[p]);
            float2 fv = __half22float2(hv[p]);
            ks[lr][lc + 2 * p] = fk.x; ks[lr][lc + 2 * p + 1] = fk.y;
            vs[lr][lc + 2 * p] = fv.x; vs[lr][lc + 2 * p + 1] = fv.y;
        }
        __syncthreads();
#pragma unroll
        for (int nn = 0; nn < 32; nn++) {
            float ra[4], rb[4];
#pragma unroll
            for (int i = 0; i < 4; i++) ra[i] = ks[ty * 4 + i][nn];
#pragma unroll
            for (int j = 0; j < 4; j++) rb[j] = vs[tx * 4 + j][nn];
#pragma unroll
            for (int i = 0; i < 4; i++)
#pragma unroll
                for (int j = 0; j < 4; j++)
                    acc[i][j] = fmaf(ra[i], rb[j], acc[i][j]);
        }
        __syncthreads();
    }
    float* Mp = g_M + (size_t)bh * HD * HD;
#pragma unroll
    for (int i = 0; i < 4; i++)
#pragma unroll
        for (int j = 0; j < 4; j++)
            atomicAdd(&Mp[(ty * 4 + i) * HD + tx * 4 + j], acc[i][j]);
}

// ---------------------------------------------------------------------------
// K4: os_t[b][n][h*64+d'] = fp16( spike( 0.25 * sum_d q[b,hd+d,n]*M[b,h,d,d'] ) )
// grid (8 ntiles, 64 bh), 256 thr
// ---------------------------------------------------------------------------
__global__ __launch_bounds__(256)
void qm_kernel() {
    const int bh = blockIdx.y;
    const int b = bh >> 3, h = bh & 7;
    const int tile_n = blockIdx.x * 128;
    const __half* Qb = g_q + (size_t)b * CH * NPIX + (size_t)h * HD * NPIX;

    __shared__ float Ms[64 * 64];
    __shared__ float qs[64][128];

    const int tid = threadIdx.x;
    const float4* Msrc = (const float4*)(g_M + (size_t)bh * HD * HD);
#pragma unroll
    for (int l = 0; l < 4; l++)
        ((float4*)Ms)[tid + l * 256] = Msrc[tid + l * 256];

#pragma unroll
    for (int l = 0; l < 4; l++) {
        int fi = tid + l * 256;           // 1024 chunks of 8 halves
        int row = fi >> 4, c8 = (fi & 15) * 8;
        int4 raw = *(const int4*)(Qb + (size_t)row * NPIX + tile_n + c8);
        const __half2* hq = (const __half2*)&raw;
#pragma unroll
        for (int p = 0; p < 4; p++) {
            float2 f = __half22float2(hq[p]);
            qs[row][c8 + 2 * p] = f.x; qs[row][c8 + 2 * p + 1] = f.y;
        }
    }
    __syncthreads();

    const int tx = tid & 31, ty = tid >> 5;   // n = tile_n+tx*4.., d' = ty*8..
    float acc[8][4];
#pragma unroll
    for (int i = 0; i < 8; i++)
#pragma unroll
        for (int j = 0; j < 4; j++) acc[i][j] = 0.0f;

#pragma unroll 8
    for (int k = 0; k < 64; k++) {
        float rb[4];
        *(float4*)rb = *(float4*)&qs[k][tx * 4];
#pragma unroll
        for (int i = 0; i < 8; i++) {
            float ra = Ms[k * 64 + ty * 8 + i];
#pragma unroll
            for (int j = 0; j < 4; j++)
                acc[i][j] = fmaf(ra, rb[j], acc[i][j]);
        }
    }

    __half* Ob = g_os_t + (size_t)b * NPIX * CH;
#pragma unroll
    for (int j = 0; j < 4; j++) {
        int n = tile_n + tx * 4 + j;
        uint32_t hp[4];
#pragma unroll
        for (int i2 = 0; i2 < 4; i2++) {
            float y0 = spikef(acc[2 * i2][j] * 0.25f);
            float y1 = spikef(acc[2 * i2 + 1][j] * 0.25f);
            __half2 hh = __floats2half2_rn(y0, y1);
            hp[i2] = *reinterpret_cast<uint32_t*>(&hh);
        }
        *(int4*)(Ob + (size_t)n * CH + h * 64 + ty * 8) = *(int4*)hp;
    }
}

// ---------------------------------------------------------------------------
// launch
// ---------------------------------------------------------------------------
static constexpr int CONV_SMEM = 2 * 32768 + 1024;   // 66560

extern "C" void kernel_launch(void* const* d_in, const int* in_sizes, int n_in,
                              void* d_out, int out_size) {
    (void)in_sizes; (void)n_in; (void)out_size;
    const float* x  = (const float*)d_in[0];
    const float* qw = (const float*)d_in[1];
    const float* qg = (const float*)d_in[2];
    const float* qb = (const float*)d_in[3];
    const float* qm = (const float*)d_in[4];
    const float* qv = (const float*)d_in[5];
    const float* kw = (const float*)d_in[6];
    const float* kg = (const float*)d_in[7];
    const float* kb = (const float*)d_in[8];
    const float* km = (const float*)d_in[9];
    const float* kv = (const float*)d_in[10];
    const float* vw = (const float*)d_in[11];
    const float* vg = (const float*)d_in[12];
    const float* vb = (const float*)d_in[13];
    const float* vm = (const float*)d_in[14];
    const float* vv = (const float*)d_in[15];
    const float* pw = (const float*)d_in[16];
    const float* pg = (const float*)d_in[17];
    const float* pb = (const float*)d_in[18];
    const float* pm = (const float*)d_in[19];
    const float* pv = (const float*)d_in[20];
    float* out = (float*)d_out;

    __half *xs_t, *q, *k, *v, *os_t, *wsp;
    cudaGetSymbolAddress((void**)&xs_t, g_xs_t);
    cudaGetSymbolAddress((void**)&q,    g_q);
    cudaGetSymbolAddress((void**)&k,    g_k);
    cudaGetSymbolAddress((void**)&v,    g_v);
    cudaGetSymbolAddress((void**)&os_t, g_os_t);
    cudaGetSymbolAddress((void**)&wsp,  g_wsplit);

    static bool attr_done = false;
    if (!attr_done) {
        cudaFuncSetAttribute(conv_mma_kernel<true,  __half>,
                             cudaFuncAttributeMaxDynamicSharedMemorySize, CONV_SMEM);
        cudaFuncSetAttribute(conv_mma_kernel<false, float>,
                             cudaFuncAttributeMaxDynamicSharedMemorySize, CONV_SMEM);
        attr_done = true;
    }

    wsplit_kernel<<<dim3(1024, 4), 256>>>(qw, kw, vw, pw);
    spike_t_kernel<<<dim3(32, 16, 8), dim3(32, 8)>>>(x);

    dim3 cgrid(8, 4, 8);
    const size_t WS = (size_t)512 * 1024;
    conv_mma_kernel<true, __half><<<cgrid, 256, CONV_SMEM>>>(wsp + 0 * WS, xs_t, qg, qb, qm, qv, q);
    conv_mma_kernel<true, __half><<<cgrid, 256, CONV_SMEM>>>(wsp + 1 * WS, xs_t, kg, kb, km, kv, k);
    conv_mma_kernel<true, __half><<<cgrid, 256, CONV_SMEM>>>(wsp + 2 * WS, xs_t, vg, vb, vm, vv, v);

    zero_M_kernel<<<256, 256>>>();
    ktv_kernel<<<dim3(4, 64), 256>>>();
    qm_kernel <<<dim3(8, 64), 256>>>();

    conv_mma_kernel<false, float><<<cgrid, 256, CONV_SMEM>>>(wsp + 3 * WS, os_t, pg, pb, pm, pv, out);
}

// round 5
// speedup vs baseline: 2.3598x; 1.0566x over previous
#include <cuda_runtime.h>
#include <cuda_fp16.h>
#include <cstdint>

#define BATCH 8
#define CH    512
#define NPIX  1024
#define HEADS 8
#define HD    64
#define EPSBN 1e-5f

// ---------------- static scratch (no allocs allowed) ----------------
__device__ __half g_xs_t [BATCH * NPIX * CH];   // spiked x, transposed [b][n][c]
__device__ __half g_q    [BATCH * CH * NPIX];   // [b][c][n]
__device__ __half g_k    [BATCH * CH * NPIX];
__device__ __half g_v    [BATCH * CH * NPIX];
__device__ __half g_os_t [BATCH * NPIX * CH];   // spiked attn out, [b][n][c]
__device__ float  g_M    [BATCH * HEADS * HD * HD];
__device__ __half g_wsplit[4 * CH * (2 * CH)];  // per weight: [o][c<512]=hi, [o][512+c]=lo
__device__ float  g_bns[4 * CH];                // BN scale  per conv/row (q,k,v,p)
__device__ float  g_bnb[4 * CH];                // BN beta   per conv/row

__device__ __forceinline__ float spikef(float x) {
    x = fminf(fmaxf(x, 0.0f), 4.0f);
    return rintf(x) * 0.25f;           // round-half-even == jnp.round
}

// ---------------- PTX helpers (baseline sm_80+ features only) ----------------
__device__ __forceinline__ uint32_t smem_u32(const void* p) {
    uint32_t a;
    asm("{ .reg .u64 t; cvta.to.shared.u64 t, %1; cvt.u32.u64 %0, t; }" : "=r"(a) : "l"(p));
    return a;
}
#define CP_ASYNC16(dst, src) \
    asm volatile("cp.async.cg.shared.global [%0], [%1], 16;" :: "r"(dst), "l"(src))
#define CP_COMMIT()  asm volatile("cp.async.commit_group;" ::: "memory")
#define CP_WAIT1()   asm volatile("cp.async.wait_group 1;" ::: "memory")
#define CP_WAIT0()   asm volatile("cp.async.wait_group 0;" ::: "memory")

__device__ __forceinline__ void ldsm_x4(uint32_t& r0, uint32_t& r1, uint32_t& r2, uint32_t& r3,
                                        uint32_t addr) {
    asm volatile("ldmatrix.sync.aligned.m8n8.x4.shared.b16 {%0,%1,%2,%3}, [%4];"
                 : "=r"(r0), "=r"(r1), "=r"(r2), "=r"(r3) : "r"(addr));
}
__device__ __forceinline__ void mma16816(float* d, const uint32_t* a, const uint32_t* b) {
    asm volatile(
        "mma.sync.aligned.m16n8k16.row.col.f32.f16.f16.f32 "
        "{%0,%1,%2,%3},{%4,%5,%6,%7},{%8,%9},{%0,%1,%2,%3};"
        : "+f"(d[0]), "+f"(d[1]), "+f"(d[2]), "+f"(d[3])
        : "r"(a[0]), "r"(a[1]), "r"(a[2]), "r"(a[3]), "r"(b[0]), "r"(b[1]));
}
#define SW128(off) ((off) ^ (((off) >> 3) & 0x70))

// ---------------------------------------------------------------------------
// K0a: split each fp32 weight into two fp16 halves, K-concatenated
// ---------------------------------------------------------------------------
__global__ void wsplit_kernel(const float* __restrict__ w0, const float* __restrict__ w1,
                              const float* __restrict__ w2, const float* __restrict__ w3) {
    const float* W[4] = {w0, w1, w2, w3};
    int wi = blockIdx.y;
    int idx = blockIdx.x * 256 + threadIdx.x;      // 0 .. 262143
    int o = idx >> 9, c = idx & 511;
    float w = W[wi][o * 512 + c];
    __half h1 = __float2half_rn(w);
    __half h2 = __float2half_rn(w - __half2float(h1));
    __half* dst = g_wsplit + (size_t)(wi * 512 + o) * 1024;
    dst[c]       = h1;
    dst[512 + c] = h2;
}

// ---------------------------------------------------------------------------
// K0b: precompute BN scale/beta tables for all 4 convs
// ---------------------------------------------------------------------------
__global__ void bn_prep_kernel(const float* qg, const float* qb, const float* qm, const float* qv,
                               const float* kg, const float* kb, const float* km, const float* kv,
                               const float* vg, const float* vb, const float* vm, const float* vv,
                               const float* pg, const float* pb, const float* pm, const float* pv) {
    int idx = blockIdx.x * 256 + threadIdx.x;      // 0..2047
    int wi = idx >> 9, c = idx & 511;
    const float* G[4] = {qg, kg, vg, pg};
    const float* Bb[4] = {qb, kb, vb, pb};
    const float* Mm[4] = {qm, km, vm, pm};
    const float* Vv[4] = {qv, kv, vv, pv};
    float s = G[wi][c] / sqrtf(Vv[wi][c] + EPSBN);
    g_bns[idx] = s;
    g_bnb[idx] = Bb[wi][c] - Mm[wi][c] * s;
}

// ---------------------------------------------------------------------------
// K1: xs_t[b][n][c] = fp16(spike(x[b][c][n]))  -- transpose via smem tile
// ---------------------------------------------------------------------------
__global__ void spike_t_kernel(const float* __restrict__ x) {
    __shared__ float tile[32][33];
    int b = blockIdx.z, n0 = blockIdx.x * 32, c0 = blockIdx.y * 32;
    int tx = threadIdx.x, ty = threadIdx.y;
    const float* xb = x + (size_t)b * CH * NPIX;
#pragma unroll
    for (int i = 0; i < 4; i++)
        tile[ty + i * 8][tx] = spikef(xb[(size_t)(c0 + ty + i * 8) * NPIX + n0 + tx]);
    __syncthreads();
    __half* ob = g_xs_t + (size_t)b * NPIX * CH;
#pragma unroll
    for (int i = 0; i < 4; i++)
        ob[(size_t)(n0 + ty + i * 8) * CH + c0 + tx] = __float2half_rn(tile[tx][ty + i * 8]);
}

// ---------------------------------------------------------------------------
// K2: mma.sync conv_bn GEMM, 3-stage cp.async pipeline, 1 sync per K-chunk.
// D[o,n] = sum_{k<1024} Wsp[o,k] * Bact[n, k%512]; BN (+spike) epilogue.
// 128x128 tile, BK=64, 8 warps (2m x 4n), warp tile 64x32.
// FUSED: M spans 3 convs (q,k,v rows 0..1535), output routed by row>>9.
// ---------------------------------------------------------------------------
template <bool SPIKE, bool FUSED, typename OutT>
__global__ __launch_bounds__(256, 2)
void conv_mma_kernel(const __half* __restrict__ Wsp,   // [M][1024]
                     const __half* __restrict__ Bact,  // [B][1024][512]
                     const float* __restrict__ bns,    // [M] scale
                     const float* __restrict__ bnb,    // [M] beta
                     OutT* __restrict__ Yq, OutT* __restrict__ Yk, OutT* __restrict__ Yv)
{
    extern __shared__ char dsm[];
    const int tid  = threadIdx.x;
    const int wid  = tid >> 5, lane = tid & 31;
    const int b      = blockIdx.z;
    const int tile_n = blockIdx.x * 128;
    const int tile_m = blockIdx.y * 128;
    const int warp_m = (wid & 1) * 64;
    const int warp_n = (wid >> 1) * 32;

    OutT* Yb;
    if (FUSED) {
        const int wi = tile_m >> 9;
        Yb = (wi == 0) ? Yq : ((wi == 1) ? Yk : Yv);
    } else {
        Yb = Yq;
    }

    uint32_t base = (smem_u32(dsm) + 1023) & ~1023u;
    uint32_t sA[3], sB[3];
#pragma unroll
    for (int s = 0; s < 3; s++) { sA[s] = base + s * 32768; sB[s] = sA[s] + 16384; }

    const __half* Bb   = Bact + (size_t)b * NPIX * CH;
    const __half* Arow = Wsp + (size_t)(tile_m + (tid >> 1)) * 1024 + (tid & 1) * 32;
    const __half* Brow = Bb  + (size_t)(tile_n + (tid >> 1)) * 512  + (tid & 1) * 32;

    uint32_t stg[4];
#pragma unroll
    for (int i = 0; i < 4; i++) {
        uint32_t off = (uint32_t)(tid >> 1) * 128 + ((tid & 1) * 4 + i) * 16;
        stg[i] = SW128(off);
    }

    const uint32_t aoff = (uint32_t)(warp_m + (lane & 15)) * 128 + (lane >> 4) * 16;
    const uint32_t boff = (uint32_t)(warp_n + ((lane >> 4) & 1) * 8 + (lane & 7)) * 128
                        + ((lane >> 3) & 1) * 16;

    float acc[4][4][4];
#pragma unroll
    for (int mt = 0; mt < 4; mt++)
#pragma unroll
        for (int nt = 0; nt < 4; nt++)
#pragma unroll
            for (int e = 0; e < 4; e++) acc[mt][nt][e] = 0.0f;

    // prologue: stages 0,1 <- chunks 0,1
#pragma unroll
    for (int st = 0; st < 2; st++) {
        const __half* An = Arow + st * 64;
        const __half* Bn = Brow + st * 64;     // (st & 7) == st for st<2
#pragma unroll
        for (int i = 0; i < 4; i++) {
            CP_ASYNC16(sA[st] + stg[i], An + i * 8);
            CP_ASYNC16(sB[st] + stg[i], Bn + i * 8);
        }
        CP_COMMIT();
    }

#pragma unroll 1
    for (int ch = 0; ch < 16; ch++) {
        if (ch < 15) { CP_WAIT1(); } else { CP_WAIT0(); }
        __syncthreads();                       // chunk ch visible; iter ch-1 readers done
        if (ch < 14) {
            const int st = (ch + 2) % 3;
            const __half* An = Arow + (size_t)(ch + 2) * 64;
            const __half* Bn = Brow + (size_t)((ch + 2) & 7) * 64;
#pragma unroll
            for (int i = 0; i < 4; i++) {
                CP_ASYNC16(sA[st] + stg[i], An + i * 8);
                CP_ASYNC16(sB[st] + stg[i], Bn + i * 8);
            }
            CP_COMMIT();
        }

        const uint32_t A0 = sA[ch % 3], B0 = sB[ch % 3];
#pragma unroll
        for (int s = 0; s < 4; s++) {
            uint32_t af[4][4], bf[2][4];
#pragma unroll
            for (int mt = 0; mt < 4; mt++)
                ldsm_x4(af[mt][0], af[mt][1], af[mt][2], af[mt][3],
                        A0 + SW128(aoff + mt * 2048 + s * 32));
#pragma unroll
            for (int p = 0; p < 2; p++)
                ldsm_x4(bf[p][0], bf[p][1], bf[p][2], bf[p][3],
                        B0 + SW128(boff + p * 2048 + s * 32));
#pragma unroll
            for (int mt = 0; mt < 4; mt++)
#pragma unroll
                for (int nt = 0; nt < 4; nt++)
                    mma16816(acc[mt][nt], af[mt], &bf[nt >> 1][(nt & 1) * 2]);
        }
    }

    // -------- epilogue: BN (+spike), direct register->gmem --------
    const int r0 = lane >> 2;
    const int c0 = (lane & 3) * 2;
#pragma unroll
    for (int mt = 0; mt < 4; mt++) {
#pragma unroll
        for (int half = 0; half < 2; half++) {
            const int o = tile_m + warp_m + mt * 16 + r0 + half * 8;   // global M row
            const float s    = bns[o];
            const float beta = bnb[o];
            OutT* yrow = Yb + ((size_t)b * 512 + (o & 511)) * 1024;
#pragma unroll
            for (int nt = 0; nt < 4; nt++) {
                const int n = tile_n + warp_n + nt * 8 + c0;
                float y0 = fmaf(acc[mt][nt][half * 2 + 0], s, beta);
                float y1 = fmaf(acc[mt][nt][half * 2 + 1], s, beta);
                if (SPIKE) {
                    __half2 hh = __floats2half2_rn(spikef(y0), spikef(y1));
                    *reinterpret_cast<__half2*>((__half*)yrow + n) = hh;
                } else {
                    *reinterpret_cast<float2*>((float*)yrow + n) = make_float2(y0, y1);
                }
            }
        }
    }
}

// ---------------------------------------------------------------------------
// K3a: zero M
// ---------------------------------------------------------------------------
__global__ void zero_M_kernel() {
    ((float4*)g_M)[blockIdx.x * 256 + threadIdx.x] = make_float4(0.f, 0.f, 0.f, 0.f);
}

// ---------------------------------------------------------------------------
// K3b: M[b,h,d,d'] += sum_n k[b,hd+d,n] * v[b,hd+d',n]  (fp16 in, exact fp32 acc)
// ---------------------------------------------------------------------------
__global__ __launch_bounds__(256)
void ktv_kernel() {
    const int bh = blockIdx.y;
    const int b = bh >> 3, h = bh & 7;
    const __half* Kb = g_k + (size_t)b * CH * NPIX + (size_t)h * HD * NPIX;
    const __half* Vb = g_v + (size_t)b * CH * NPIX + (size_t)h * HD * NPIX;

    __shared__ float ks[64][33];
    __shared__ float vs[64][33];

    const int tid = threadIdx.x;
    const int tx = tid & 15, ty = tid >> 4;
    const int lr = tid >> 2, lc = (tid & 3) * 8;

    float acc[4][4];
#pragma unroll
    for (int i = 0; i < 4; i++)
#pragma unroll
        for (int j = 0; j < 4; j++) acc[i][j] = 0.0f;

    const int n_beg = blockIdx.x * 256;
    for (int n0 = n_beg; n0 < n_beg + 256; n0 += 32) {
        int4 rk = *(const int4*)(Kb + (size_t)lr * NPIX + n0 + lc);
        int4 rv = *(const int4*)(Vb + (size_t)lr * NPIX + n0 + lc);
        const __half2* hk = (const __half2*)&rk;
        const __half2* hv = (const __half2*)&rv;
#pragma unroll
        for (int p = 0; p < 4; p++) {
            float2 fk = __half22float2(hk[p]);
            float2 fv = __half22float2(hv[p]);
            ks[lr][lc + 2 * p] = fk.x; ks[lr][lc + 2 * p + 1] = fk.y;
            vs[lr][lc + 2 * p] = fv.x; vs[lr][lc + 2 * p + 1] = fv.y;
        }
        __syncthreads();
#pragma unroll
        for (int nn = 0; nn < 32; nn++) {
            float ra[4], rb[4];
#pragma unroll
            for (int i = 0; i < 4; i++) ra[i] = ks[ty * 4 + i][nn];
#pragma unroll
            for (int j = 0; j < 4; j++) rb[j] = vs[tx * 4 + j][nn];
#pragma unroll
            for (int i = 0; i < 4; i++)
#pragma unroll
                for (int j = 0; j < 4; j++)
                    acc[i][j] = fmaf(ra[i], rb[j], acc[i][j]);
        }
        __syncthreads();
    }
    float* Mp = g_M + (size_t)bh * HD * HD;
#pragma unroll
    for (int i = 0; i < 4; i++)
#pragma unroll
        for (int j = 0; j < 4; j++)
            atomicAdd(&Mp[(ty * 4 + i) * HD + tx * 4 + j], acc[i][j]);
}

// ---------------------------------------------------------------------------
// K4: os_t[b][n][h*64+d'] = fp16( spike( 0.25 * sum_d q[b,hd+d,n]*M[b,h,d,d'] ) )
// ---------------------------------------------------------------------------
__global__ __launch_bounds__(256)
void qm_kernel() {
    const int bh = blockIdx.y;
    const int b = bh >> 3, h = bh & 7;
    const int tile_n = blockIdx.x * 128;
    const __half* Qb = g_q + (size_t)b * CH * NPIX + (size_t)h * HD * NPIX;

    __shared__ float Ms[64 * 64];
    __shared__ float qs[64][128];

    const int tid = threadIdx.x;
    const float4* Msrc = (const float4*)(g_M + (size_t)bh * HD * HD);
#pragma unroll
    for (int l = 0; l < 4; l++)
        ((float4*)Ms)[tid + l * 256] = Msrc[tid + l * 256];

#pragma unroll
    for (int l = 0; l < 4; l++) {
        int fi = tid + l * 256;
        int row = fi >> 4, c8 = (fi & 15) * 8;
        int4 raw = *(const int4*)(Qb + (size_t)row * NPIX + tile_n + c8);
        const __half2* hq = (const __half2*)&raw;
#pragma unroll
        for (int p = 0; p < 4; p++) {
            float2 f = __half22float2(hq[p]);
            qs[row][c8 + 2 * p] = f.x; qs[row][c8 + 2 * p + 1] = f.y;
        }
    }
    __syncthreads();

    const int tx = tid & 31, ty = tid >> 5;
    float acc[8][4];
#pragma unroll
    for (int i = 0; i < 8; i++)
#pragma unroll
        for (int j = 0; j < 4; j++) acc[i][j] = 0.0f;

#pragma unroll 8
    for (int k = 0; k < 64; k++) {
        float rb[4];
        *(float4*)rb = *(float4*)&qs[k][tx * 4];
#pragma unroll
        for (int i = 0; i < 8; i++) {
            float ra = Ms[k * 64 + ty * 8 + i];
#pragma unroll
            for (int j = 0; j < 4; j++)
                acc[i][j] = fmaf(ra, rb[j], acc[i][j]);
        }
    }

    __half* Ob = g_os_t + (size_t)b * NPIX * CH;
#pragma unroll
    for (int j = 0; j < 4; j++) {
        int n = tile_n + tx * 4 + j;
        uint32_t hp[4];
#pragma unroll
        for (int i2 = 0; i2 < 4; i2++) {
            float y0 = spikef(acc[2 * i2][j] * 0.25f);
            float y1 = spikef(acc[2 * i2 + 1][j] * 0.25f);
            __half2 hh = __floats2half2_rn(y0, y1);
            hp[i2] = *reinterpret_cast<uint32_t*>(&hh);
        }
        *(int4*)(Ob + (size_t)n * CH + h * 64 + ty * 8) = *(int4*)hp;
    }
}

// ---------------------------------------------------------------------------
// launch
// ---------------------------------------------------------------------------
static constexpr int CONV_SMEM = 3 * 32768 + 1024;   // 99328

extern "C" void kernel_launch(void* const* d_in, const int* in_sizes, int n_in,
                              void* d_out, int out_size) {
    (void)in_sizes; (void)n_in; (void)out_size;
    const float* x  = (const float*)d_in[0];
    const float* qw = (const float*)d_in[1];
    const float* qg = (const float*)d_in[2];
    const float* qb = (const float*)d_in[3];
    const float* qm = (const float*)d_in[4];
    const float* qv = (const float*)d_in[5];
    const float* kw = (const float*)d_in[6];
    const float* kg = (const float*)d_in[7];
    const float* kb = (const float*)d_in[8];
    const float* km = (const float*)d_in[9];
    const float* kv = (const float*)d_in[10];
    const float* vw = (const float*)d_in[11];
    const float* vg = (const float*)d_in[12];
    const float* vb = (const float*)d_in[13];
    const float* vm = (const float*)d_in[14];
    const float* vv = (const float*)d_in[15];
    const float* pw = (const float*)d_in[16];
    const float* pg = (const float*)d_in[17];
    const float* pb = (const float*)d_in[18];
    const float* pm = (const float*)d_in[19];
    const float* pv = (const float*)d_in[20];
    float* out = (float*)d_out;

    __half *xs_t, *q, *k, *v, *os_t, *wsp;
    float *bns, *bnb;
    cudaGetSymbolAddress((void**)&xs_t, g_xs_t);
    cudaGetSymbolAddress((void**)&q,    g_q);
    cudaGetSymbolAddress((void**)&k,    g_k);
    cudaGetSymbolAddress((void**)&v,    g_v);
    cudaGetSymbolAddress((void**)&os_t, g_os_t);
    cudaGetSymbolAddress((void**)&wsp,  g_wsplit);
    cudaGetSymbolAddress((void**)&bns,  g_bns);
    cudaGetSymbolAddress((void**)&bnb,  g_bnb);

    static bool attr_done = false;
    if (!attr_done) {
        cudaFuncSetAttribute(conv_mma_kernel<true,  true,  __half>,
                             cudaFuncAttributeMaxDynamicSharedMemorySize, CONV_SMEM);
        cudaFuncSetAttribute(conv_mma_kernel<false, false, float>,
                             cudaFuncAttributeMaxDynamicSharedMemorySize, CONV_SMEM);
        attr_done = true;
    }

    wsplit_kernel<<<dim3(1024, 4), 256>>>(qw, kw, vw, pw);
    bn_prep_kernel<<<8, 256>>>(qg, qb, qm, qv, kg, kb, km, kv,
                               vg, vb, vm, vv, pg, pb, pm, pv);
    spike_t_kernel<<<dim3(32, 16, 8), dim3(32, 8)>>>(x);

    // fused q,k,v conv: M = 1536
    conv_mma_kernel<true, true, __half><<<dim3(8, 12, 8), 256, CONV_SMEM>>>(
        wsp, xs_t, bns, bnb, q, k, v);

    zero_M_kernel<<<256, 256>>>();
    ktv_kernel<<<dim3(4, 64), 256>>>();
    qm_kernel <<<dim3(8, 64), 256>>>();

    const size_t WS = (size_t)512 * 1024;
    conv_mma_kernel<false, false, float><<<dim3(8, 4, 8), 256, CONV_SMEM>>>(
        wsp + 3 * WS, os_t, bns + 3 * CH, bnb + 3 * CH, out, nullptr, nullptr);
}

// round 7
// speedup vs baseline: 2.5529x; 1.0818x over previous
#include <cuda_runtime.h>
#include <cuda_fp16.h>
#include <cstdint>

#define BATCH 8
#define CH    512
#define NPIX  1024
#define HEADS 8
#define HD    64
#define EPSBN 1e-5f

// ---------------- static scratch (no allocs allowed) ----------------
__device__ __half g_xs_t [BATCH * NPIX * CH];   // spiked x, transposed [b][n][c]
__device__ __half g_q    [BATCH * CH * NPIX];   // [b][c][n]
__device__ __half g_k    [BATCH * CH * NPIX];
__device__ __half g_v    [BATCH * CH * NPIX];
__device__ __half g_os_t [BATCH * NPIX * CH];   // spiked attn out, [b][n][c]
__device__ float  g_Mpart[2 * BATCH * HEADS * HD * HD];  // [nsplit][bh][64][64]
__device__ __half g_wsplit[4 * CH * (2 * CH)];  // per weight: [o][c<512]=hi, [o][512+c]=lo
__device__ float  g_bns[4 * CH];
__device__ float  g_bnb[4 * CH];

__device__ __forceinline__ float spikef(float x) {
    x = fminf(fmaxf(x, 0.0f), 4.0f);
    return rintf(x) * 0.25f;           // round-half-even == jnp.round
}

// ---------------- PTX helpers (baseline sm_80+ features only) ----------------
__device__ __forceinline__ uint32_t smem_u32(const void* p) {
    uint32_t a;
    asm("{ .reg .u64 t; cvta.to.shared.u64 t, %1; cvt.u32.u64 %0, t; }" : "=r"(a) : "l"(p));
    return a;
}
#define CP_ASYNC16(dst, src) \
    asm volatile("cp.async.cg.shared.global [%0], [%1], 16;" :: "r"(dst), "l"(src))
#define CP_COMMIT()  asm volatile("cp.async.commit_group;" ::: "memory")
#define CP_WAIT1()   asm volatile("cp.async.wait_group 1;" ::: "memory")
#define CP_WAIT0()   asm volatile("cp.async.wait_group 0;" ::: "memory")

__device__ __forceinline__ void ldsm_x4(uint32_t& r0, uint32_t& r1, uint32_t& r2, uint32_t& r3,
                                        uint32_t addr) {
    asm volatile("ldmatrix.sync.aligned.m8n8.x4.shared.b16 {%0,%1,%2,%3}, [%4];"
                 : "=r"(r0), "=r"(r1), "=r"(r2), "=r"(r3) : "r"(addr));
}
__device__ __forceinline__ void mma16816(float* d, const uint32_t* a, const uint32_t* b) {
    asm volatile(
        "mma.sync.aligned.m16n8k16.row.col.f32.f16.f16.f32 "
        "{%0,%1,%2,%3},{%4,%5,%6,%7},{%8,%9},{%0,%1,%2,%3};"
        : "+f"(d[0]), "+f"(d[1]), "+f"(d[2]), "+f"(d[3])
        : "r"(a[0]), "r"(a[1]), "r"(a[2]), "r"(a[3]), "r"(b[0]), "r"(b[1]));
}
#define SW128(off) ((off) ^ (((off) >> 3) & 0x70))

// ---------------------------------------------------------------------------
// K0a: split each fp32 weight into two fp16 halves, K-concatenated
// ---------------------------------------------------------------------------
__global__ void wsplit_kernel(const float* __restrict__ w0, const float* __restrict__ w1,
                              const float* __restrict__ w2, const float* __restrict__ w3) {
    const float* W[4] = {w0, w1, w2, w3};
    int wi = blockIdx.y;
    int idx = blockIdx.x * 256 + threadIdx.x;
    int o = idx >> 9, c = idx & 511;
    float w = W[wi][o * 512 + c];
    __half h1 = __float2half_rn(w);
    __half h2 = __float2half_rn(w - __half2float(h1));
    __half* dst = g_wsplit + (size_t)(wi * 512 + o) * 1024;
    dst[c]       = h1;
    dst[512 + c] = h2;
}

// ---------------------------------------------------------------------------
// K0b: precompute BN scale/beta tables for all 4 convs
// ---------------------------------------------------------------------------
__global__ void bn_prep_kernel(const float* qg, const float* qb, const float* qm, const float* qv,
                               const float* kg, const float* kb, const float* km, const float* kv,
                               const float* vg, const float* vb, const float* vm, const float* vv,
                               const float* pg, const float* pb, const float* pm, const float* pv) {
    int idx = blockIdx.x * 256 + threadIdx.x;      // 0..2047
    int wi = idx >> 9, c = idx & 511;
    const float* G[4] = {qg, kg, vg, pg};
    const float* Bb[4] = {qb, kb, vb, pb};
    const float* Mm[4] = {qm, km, vm, pm};
    const float* Vv[4] = {qv, kv, vv, pv};
    float s = G[wi][c] / sqrtf(Vv[wi][c] + EPSBN);
    g_bns[idx] = s;
    g_bnb[idx] = Bb[wi][c] - Mm[wi][c] * s;
}

// ---------------------------------------------------------------------------
// K1: xs_t[b][n][c] = fp16(spike(x[b][c][n]))  -- transpose via smem tile
// ---------------------------------------------------------------------------
__global__ void spike_t_kernel(const float* __restrict__ x) {
    __shared__ float tile[32][33];
    int b = blockIdx.z, n0 = blockIdx.x * 32, c0 = blockIdx.y * 32;
    int tx = threadIdx.x, ty = threadIdx.y;
    const float* xb = x + (size_t)b * CH * NPIX;
#pragma unroll
    for (int i = 0; i < 4; i++)
        tile[ty + i * 8][tx] = spikef(xb[(size_t)(c0 + ty + i * 8) * NPIX + n0 + tx]);
    __syncthreads();
    __half* ob = g_xs_t + (size_t)b * NPIX * CH;
#pragma unroll
    for (int i = 0; i < 4; i++)
        ob[(size_t)(n0 + ty + i * 8) * CH + c0 + tx] = __float2half_rn(tile[tx][ty + i * 8]);
}

// ---------------------------------------------------------------------------
// K2: mma.sync conv_bn GEMM. Tile M=128, N=64, BK=64, 3-stage cp.async,
// canonical single-barrier pipeline (issue ch+2 -> compute ch -> wait ch+1 -> sync).
// 8 warps (4m x 2n), warp tile 32x32 -> 32 acc regs, target 3 CTAs/SM.
// ---------------------------------------------------------------------------
template <bool SPIKE, bool FUSED, typename OutT>
__global__ __launch_bounds__(256, 3)
void conv_mma_kernel(const __half* __restrict__ Wsp,   // [M][1024]
                     const __half* __restrict__ Bact,  // [B][1024][512]
                     const float* __restrict__ bns,
                     const float* __restrict__ bnb,
                     OutT* __restrict__ Yq, OutT* __restrict__ Yk, OutT* __restrict__ Yv)
{
    extern __shared__ char dsm[];
    const int tid  = threadIdx.x;
    const int wid  = tid >> 5, lane = tid & 31;
    const int b      = blockIdx.z;
    const int tile_n = blockIdx.x * 64;
    const int tile_m = blockIdx.y * 128;
    const int warp_m = (wid & 3) * 32;
    const int warp_n = (wid >> 2) * 32;

    OutT* Yb;
    if (FUSED) {
        const int wi = tile_m >> 9;
        Yb = (wi == 0) ? Yq : ((wi == 1) ? Yk : Yv);
    } else {
        Yb = Yq;
    }

    uint32_t base = (smem_u32(dsm) + 1023) & ~1023u;
    uint32_t sA[3], sB[3];
#pragma unroll
    for (int s = 0; s < 3; s++) { sA[s] = base + s * 24576; sB[s] = sA[s] + 16384; }

    const __half* Bb   = Bact + (size_t)b * NPIX * CH;
    const __half* Arow = Wsp + (size_t)(tile_m + (tid >> 1)) * 1024 + (tid & 1) * 32;
    const __half* Brow = Bb  + (size_t)(tile_n + (tid >> 2)) * 512  + (tid & 3) * 16;

    uint32_t stgA[4], stgB[2];
#pragma unroll
    for (int i = 0; i < 4; i++)
        stgA[i] = SW128((uint32_t)(tid >> 1) * 128 + ((tid & 1) * 4 + i) * 16);
#pragma unroll
    for (int i = 0; i < 2; i++)
        stgB[i] = SW128((uint32_t)(tid >> 2) * 128 + ((tid & 3) * 2 + i) * 16);

    const uint32_t aoff = (uint32_t)(warp_m + (lane & 15)) * 128 + (lane >> 4) * 16;
    const uint32_t boff = (uint32_t)(warp_n + ((lane >> 4) & 1) * 8 + (lane & 7)) * 128
                        + ((lane >> 3) & 1) * 16;

    float acc[2][4][4];
#pragma unroll
    for (int mt = 0; mt < 2; mt++)
#pragma unroll
        for (int nt = 0; nt < 4; nt++)
#pragma unroll
            for (int e = 0; e < 4; e++) acc[mt][nt][e] = 0.0f;

    // prologue: stages 0,1 <- chunks 0,1; then ensure chunk 0 visible to all
#pragma unroll
    for (int st = 0; st < 2; st++) {
#pragma unroll
        for (int i = 0; i < 4; i++) CP_ASYNC16(sA[st] + stgA[i], Arow + st * 64 + i * 8);
#pragma unroll
        for (int i = 0; i < 2; i++) CP_ASYNC16(sB[st] + stgB[i], Brow + st * 64 + i * 8);
        CP_COMMIT();
    }
    CP_WAIT1();            // chunk 0 landed (own groups); barrier publishes all threads'
    __syncthreads();

#pragma unroll 1
    for (int ch = 0; ch < 16; ch++) {
        // issue chunk ch+2 into stage (ch+2)%3 — freed by the barrier at end of iter ch-1
        if (ch < 14) {
            const int st = (ch + 2) % 3;
            const __half* An = Arow + (size_t)(ch + 2) * 64;
            const __half* Bn = Brow + (size_t)((ch + 2) & 7) * 64;
#pragma unroll
            for (int i = 0; i < 4; i++) CP_ASYNC16(sA[st] + stgA[i], An + i * 8);
#pragma unroll
            for (int i = 0; i < 2; i++) CP_ASYNC16(sB[st] + stgB[i], Bn + i * 8);
            CP_COMMIT();
        }

        // compute on chunk ch (guaranteed landed by wait+sync of iter ch-1 / prologue)
        const uint32_t A0 = sA[ch % 3], B0 = sB[ch % 3];
#pragma unroll
        for (int s = 0; s < 4; s++) {
            uint32_t af[2][4], bf[2][4];
#pragma unroll
            for (int mt = 0; mt < 2; mt++)
                ldsm_x4(af[mt][0], af[mt][1], af[mt][2], af[mt][3],
                        A0 + SW128(aoff + mt * 2048 + s * 32));
#pragma unroll
            for (int p = 0; p < 2; p++)
                ldsm_x4(bf[p][0], bf[p][1], bf[p][2], bf[p][3],
                        B0 + SW128(boff + p * 2048 + s * 32));
#pragma unroll
            for (int mt = 0; mt < 2; mt++)
#pragma unroll
                for (int nt = 0; nt < 4; nt++)
                    mma16816(acc[mt][nt], af[mt], &bf[nt >> 1][(nt & 1) * 2]);
        }

        // make chunk ch+1 ready for next iteration
        if (ch < 15) {
            if (ch < 14) { CP_WAIT1(); } else { CP_WAIT0(); }
            __syncthreads();
        }
    }

    // -------- epilogue: BN (+spike), direct register->gmem --------
    const int r0 = lane >> 2;
    const int c0 = (lane & 3) * 2;
#pragma unroll
    for (int mt = 0; mt < 2; mt++) {
#pragma unroll
        for (int half = 0; half < 2; half++) {
            const int o = tile_m + warp_m + mt * 16 + r0 + half * 8;   // global M row
            const float s    = bns[o];
            const float beta = bnb[o];
            OutT* yrow = Yb + ((size_t)b * 512 + (o & 511)) * 1024;
#pragma unroll
            for (int nt = 0; nt < 4; nt++) {
                const int n = tile_n + warp_n + nt * 8 + c0;
                float y0 = fmaf(acc[mt][nt][half * 2 + 0], s, beta);
                float y1 = fmaf(acc[mt][nt][half * 2 + 1], s, beta);
                if (SPIKE) {
                    __half2 hh = __floats2half2_rn(spikef(y0), spikef(y1));
                    *reinterpret_cast<__half2*>((__half*)yrow + n) = hh;
                } else {
                    *reinterpret_cast<float2*>((float*)yrow + n) = make_float2(y0, y1);
                }
            }
        }
    }
}

// ---------------------------------------------------------------------------
// K3: ktv via mma.sync: Mpart[ns][bh][d][d'] = sum_{n in split ns} k[d,n]*v[d',n]
// grid (2 nsplit, 64 bh), 128 thr (4 warps, 2m x 2n, warp tile 32x32), K=512.
// Exact: all partial sums are multiples of 1/16 below 2^14.
// (wait -> sync -> compute ordering: correct cross-thread visibility)
// ---------------------------------------------------------------------------
__global__ __launch_bounds__(128)
void ktv_mma_kernel() {
    __shared__ char sm[2 * 16384];
    const int tid = threadIdx.x;
    const int wid = tid >> 5, lane = tid & 31;
    const int ns = blockIdx.x, bh = blockIdx.y;
    const int b = bh >> 3, h = bh & 7;
    const int warp_m = (wid & 1) * 32;
    const int warp_n = (wid >> 1) * 32;

    uint32_t base = smem_u32(sm);
    uint32_t sK[2] = {base,        base + 8192};
    uint32_t sV[2] = {base + 16384, base + 24576};

    const __half* Kb = g_k + (size_t)b * CH * NPIX + (size_t)h * HD * NPIX + ns * 512;
    const __half* Vb = g_v + (size_t)b * CH * NPIX + (size_t)h * HD * NPIX + ns * 512;
    const __half* Krow = Kb + (size_t)(tid >> 1) * NPIX + (tid & 1) * 32;
    const __half* Vrow = Vb + (size_t)(tid >> 1) * NPIX + (tid & 1) * 32;

    uint32_t stg[4];
#pragma unroll
    for (int i = 0; i < 4; i++)
        stg[i] = SW128((uint32_t)(tid >> 1) * 128 + ((tid & 1) * 4 + i) * 16);

    const uint32_t aoff = (uint32_t)(warp_m + (lane & 15)) * 128 + (lane >> 4) * 16;
    const uint32_t boff = (uint32_t)(warp_n + ((lane >> 4) & 1) * 8 + (lane & 7)) * 128
                        + ((lane >> 3) & 1) * 16;

    float acc[2][4][4];
#pragma unroll
    for (int mt = 0; mt < 2; mt++)
#pragma unroll
        for (int nt = 0; nt < 4; nt++)
#pragma unroll
            for (int e = 0; e < 4; e++) acc[mt][nt][e] = 0.0f;

    // prologue: chunk 0
#pragma unroll
    for (int i = 0; i < 4; i++) {
        CP_ASYNC16(sK[0] + stg[i], Krow + i * 8);
        CP_ASYNC16(sV[0] + stg[i], Vrow + i * 8);
    }
    CP_COMMIT();

#pragma unroll 1
    for (int ch = 0; ch < 8; ch++) {
        __syncthreads();               // writers may reuse stage read two iters ago
        if (ch < 7) {
            const int st = (ch + 1) & 1;
#pragma unroll
            for (int i = 0; i < 4; i++) {
                CP_ASYNC16(sK[st] + stg[i], Krow + (ch + 1) * 64 + i * 8);
                CP_ASYNC16(sV[st] + stg[i], Vrow + (ch + 1) * 64 + i * 8);
            }
            CP_COMMIT();
            CP_WAIT1();
        } else {
            CP_WAIT0();
        }
        __syncthreads();               // publish chunk ch to all threads

        const uint32_t A0 = sK[ch & 1], B0 = sV[ch & 1];
#pragma unroll
        for (int s = 0; s < 4; s++) {
            uint32_t af[2][4], bf[2][4];
#pragma unroll
            for (int mt = 0; mt < 2; mt++)
                ldsm_x4(af[mt][0], af[mt][1], af[mt][2], af[mt][3],
                        A0 + SW128(aoff + mt * 2048 + s * 32));
#pragma unroll
            for (int p = 0; p < 2; p++)
                ldsm_x4(bf[p][0], bf[p][1], bf[p][2], bf[p][3],
                        B0 + SW128(boff + p * 2048 + s * 32));
#pragma unroll
            for (int mt = 0; mt < 2; mt++)
#pragma unroll
                for (int nt = 0; nt < 4; nt++)
                    mma16816(acc[mt][nt], af[mt], &bf[nt >> 1][(nt & 1) * 2]);
        }
    }

    float* Mp = g_Mpart + ((size_t)ns * 64 + bh) * 4096;
    const int r0 = lane >> 2, c0 = (lane & 3) * 2;
#pragma unroll
    for (int mt = 0; mt < 2; mt++)
#pragma unroll
        for (int half = 0; half < 2; half++) {
            const int row = warp_m + mt * 16 + r0 + half * 8;
#pragma unroll
            for (int nt = 0; nt < 4; nt++) {
                const int col = warp_n + nt * 8 + c0;
                *reinterpret_cast<float2*>(Mp + row * 64 + col) =
                    make_float2(acc[mt][nt][half * 2 + 0], acc[mt][nt][half * 2 + 1]);
            }
        }
}

// ---------------------------------------------------------------------------
// K4: os_t[b][n][h*64+d'] = fp16( spike( 0.25 * sum_d q[b,hd+d,n]*M[b,h,d,d'] ) )
// M = sum of 2 ktv partials (exact).
// ---------------------------------------------------------------------------
__global__ __launch_bounds__(256)
void qm_kernel() {
    const int bh = blockIdx.y;
    const int b = bh >> 3, h = bh & 7;
    const int tile_n = blockIdx.x * 128;
    const __half* Qb = g_q + (size_t)b * CH * NPIX + (size_t)h * HD * NPIX;

    __shared__ float Ms[64 * 64];
    __shared__ float qs[64][128];

    const int tid = threadIdx.x;
    const float4* M0 = (const float4*)(g_Mpart + (size_t)bh * 4096);
    const float4* M1 = (const float4*)(g_Mpart + (size_t)(64 + bh) * 4096);
#pragma unroll
    for (int l = 0; l < 4; l++) {
        float4 a = M0[tid + l * 256], c = M1[tid + l * 256];
        ((float4*)Ms)[tid + l * 256] =
            make_float4(a.x + c.x, a.y + c.y, a.z + c.z, a.w + c.w);
    }

#pragma unroll
    for (int l = 0; l < 4; l++) {
        int fi = tid + l * 256;
        int row = fi >> 4, c8 = (fi & 15) * 8;
        int4 raw = *(const int4*)(Qb + (size_t)row * NPIX + tile_n + c8);
        const __half2* hq = (const __half2*)&raw;
#pragma unroll
        for (int p = 0; p < 4; p++) {
            float2 f = __half22float2(hq[p]);
            qs[row][c8 + 2 * p] = f.x; qs[row][c8 + 2 * p + 1] = f.y;
        }
    }
    __syncthreads();

    const int tx = tid & 31, ty = tid >> 5;
    float acc[8][4];
#pragma unroll
    for (int i = 0; i < 8; i++)
#pragma unroll
        for (int j = 0; j < 4; j++) acc[i][j] = 0.0f;

#pragma unroll 8
    for (int k = 0; k < 64; k++) {
        float rb[4];
        *(float4*)rb = *(float4*)&qs[k][tx * 4];
#pragma unroll
        for (int i = 0; i < 8; i++) {
            float ra = Ms[k * 64 + ty * 8 + i];
#pragma unroll
            for (int j = 0; j < 4; j++)
                acc[i][j] = fmaf(ra, rb[j], acc[i][j]);
        }
    }

    __half* Ob = g_os_t + (size_t)b * NPIX * CH;
#pragma unroll
    for (int j = 0; j < 4; j++) {
        int n = tile_n + tx * 4 + j;
        uint32_t hp[4];
#pragma unroll
        for (int i2 = 0; i2 < 4; i2++) {
            float y0 = spikef(acc[2 * i2][j] * 0.25f);
            float y1 = spikef(acc[2 * i2 + 1][j] * 0.25f);
            __half2 hh = __floats2half2_rn(y0, y1);
            hp[i2] = *reinterpret_cast<uint32_t*>(&hh);
        }
        *(int4*)(Ob + (size_t)n * CH + h * 64 + ty * 8) = *(int4*)hp;
    }
}

// ---------------------------------------------------------------------------
// launch
// ---------------------------------------------------------------------------
static constexpr int CONV_SMEM = 3 * 24576 + 1024;   // 74752

extern "C" void kernel_launch(void* const* d_in, const int* in_sizes, int n_in,
                              void* d_out, int out_size) {
    (void)in_sizes; (void)n_in; (void)out_size;
    const float* x  = (const float*)d_in[0];
    const float* qw = (const float*)d_in[1];
    const float* qg = (const float*)d_in[2];
    const float* qb = (const float*)d_in[3];
    const float* qm = (const float*)d_in[4];
    const float* qv = (const float*)d_in[5];
    const float* kw = (const float*)d_in[6];
    const float* kg = (const float*)d_in[7];
    const float* kb = (const float*)d_in[8];
    const float* km = (const float*)d_in[9];
    const float* kv = (const float*)d_in[10];
    const float* vw = (const float*)d_in[11];
    const float* vg = (const float*)d_in[12];
    const float* vb = (const float*)d_in[13];
    const float* vm = (const float*)d_in[14];
    const float* vv = (const float*)d_in[15];
    const float* pw = (const float*)d_in[16];
    const float* pg = (const float*)d_in[17];
    const float* pb = (const float*)d_in[18];
    const float* pm = (const float*)d_in[19];
    const float* pv = (const float*)d_in[20];
    float* out = (float*)d_out;

    __half *xs_t, *q, *k, *v, *os_t, *wsp;
    float *bns, *bnb;
    cudaGetSymbolAddress((void**)&xs_t, g_xs_t);
    cudaGetSymbolAddress((void**)&q,    g_q);
    cudaGetSymbolAddress((void**)&k,    g_k);
    cudaGetSymbolAddress((void**)&v,    g_v);
    cudaGetSymbolAddress((void**)&os_t, g_os_t);
    cudaGetSymbolAddress((void**)&wsp,  g_wsplit);
    cudaGetSymbolAddress((void**)&bns,  g_bns);
    cudaGetSymbolAddress((void**)&bnb,  g_bnb);

    static bool attr_done = false;
    if (!attr_done) {
        cudaFuncSetAttribute(conv_mma_kernel<true,  true,  __half>,
                             cudaFuncAttributeMaxDynamicSharedMemorySize, CONV_SMEM);
        cudaFuncSetAttribute(conv_mma_kernel<false, false, float>,
                             cudaFuncAttributeMaxDynamicSharedMemorySize, CONV_SMEM);
        attr_done = true;
    }

    wsplit_kernel<<<dim3(1024, 4), 256>>>(qw, kw, vw, pw);
    bn_prep_kernel<<<8, 256>>>(qg, qb, qm, qv, kg, kb, km, kv,
                               vg, vb, vm, vv, pg, pb, pm, pv);
    spike_t_kernel<<<dim3(32, 16, 8), dim3(32, 8)>>>(x);

    // fused q,k,v conv: M = 1536, tiles (16 n, 12 m, 8 b)
    conv_mma_kernel<true, true, __half><<<dim3(16, 12, 8), 256, CONV_SMEM>>>(
        wsp, xs_t, bns, bnb, q, k, v);

    ktv_mma_kernel<<<dim3(2, 64), 128>>>();
    qm_kernel <<<dim3(8, 64), 256>>>();

    const size_t WS = (size_t)512 * 1024;
    conv_mma_kernel<false, false, float><<<dim3(16, 4, 8), 256, CONV_SMEM>>>(
        wsp + 3 * WS, os_t, bns + 3 * CH, bnb + 3 * CH, out, nullptr, nullptr);
}